// round 7
// baseline (speedup 1.0000x reference)
#include <cuda_runtime.h>
#include <cuda_bf16.h>
#include <cstdint>

#define B_   2
#define S_   2048
#define HID_ 4096
#define NH_  32
#define NKV_ 8
#define HD_  128

typedef __nv_bfloat16 bf16;

// ---------------- device scratch ----------------
__device__ bf16  g_hsh[(size_t)B_ * S_ * HID_];
__device__ bf16  g_hsl[(size_t)B_ * S_ * HID_];
__device__ bf16  g_wh [(size_t)(HID_ + 2 * NKV_ * HD_) * HID_];
__device__ bf16  g_wl [(size_t)(HID_ + 2 * NKV_ * HD_) * HID_];
__device__ bf16  g_wdh[(size_t)HID_ * HID_];
__device__ bf16  g_wdl[(size_t)HID_ * HID_];
__device__ float g_qf [(size_t)B_ * NH_ * S_ * HD_];
__device__ float g_kf [(size_t)B_ * NKV_ * S_ * HD_];
__device__ bf16  g_qh [(size_t)B_ * NH_ * S_ * HD_];
__device__ bf16  g_ql [(size_t)B_ * NH_ * S_ * HD_];
__device__ bf16  g_kh [(size_t)B_ * NKV_ * S_ * HD_];
__device__ bf16  g_kl [(size_t)B_ * NKV_ * S_ * HD_];
__device__ bf16  g_vh [(size_t)B_ * NKV_ * S_ * HD_];
__device__ bf16  g_vl [(size_t)B_ * NKV_ * S_ * HD_];
__device__ bf16  g_ch [(size_t)B_ * S_ * HID_];
__device__ bf16  g_cl [(size_t)B_ * S_ * HID_];

// ---------------- helpers ----------------
__device__ __forceinline__ void cp16(void* dst, const void* src) {
    unsigned d = (unsigned)__cvta_generic_to_shared(dst);
    asm volatile("cp.async.cg.shared.global [%0], [%1], 16;\n" :: "r"(d), "l"(src));
}
__device__ __forceinline__ void cp_commit() { asm volatile("cp.async.commit_group;\n"); }
__device__ __forceinline__ void cp_wait0()  { asm volatile("cp.async.wait_group 0;\n"); }
__device__ __forceinline__ void cp_wait1()  { asm volatile("cp.async.wait_group 1;\n"); }

__device__ __forceinline__ void ldsm4(uint32_t* r, const void* p) {
    uint32_t a = (uint32_t)__cvta_generic_to_shared(p);
    asm volatile("ldmatrix.sync.aligned.m8n8.x4.shared.b16 {%0,%1,%2,%3}, [%4];\n"
        : "=r"(r[0]), "=r"(r[1]), "=r"(r[2]), "=r"(r[3]) : "r"(a));
}
__device__ __forceinline__ void ldsm4t(uint32_t* r, const void* p) {
    uint32_t a = (uint32_t)__cvta_generic_to_shared(p);
    asm volatile("ldmatrix.sync.aligned.m8n8.x4.trans.shared.b16 {%0,%1,%2,%3}, [%4];\n"
        : "=r"(r[0]), "=r"(r[1]), "=r"(r[2]), "=r"(r[3]) : "r"(a));
}

__device__ __forceinline__ void mma16(float* c, const uint32_t* a, uint32_t b0, uint32_t b1) {
    asm volatile(
        "mma.sync.aligned.m16n8k16.row.col.f32.bf16.bf16.f32 "
        "{%0,%1,%2,%3},{%4,%5,%6,%7},{%8,%9},{%0,%1,%2,%3};\n"
        : "+f"(c[0]), "+f"(c[1]), "+f"(c[2]), "+f"(c[3])
        : "r"(a[0]), "r"(a[1]), "r"(a[2]), "r"(a[3]), "r"(b0), "r"(b1));
}

__device__ __forceinline__ uint32_t packh(float e, float o) {
    __nv_bfloat162 t = __floats2bfloat162_rn(e, o);
    return *reinterpret_cast<const uint32_t*>(&t);
}
__device__ __forceinline__ uint32_t packl(float e, float o) {
    float he = __bfloat162float(__float2bfloat16_rn(e));
    float ho = __bfloat162float(__float2bfloat16_rn(o));
    return packh(e - he, o - ho);
}
__device__ __forceinline__ void sstore(bf16* oh, bf16* ol, int i, float v) {
    bf16 h = __float2bfloat16_rn(v);
    oh[i] = h;
    ol[i] = __float2bfloat16_rn(v - __bfloat162float(h));
}

// ---------------- fused split pass ----------
#define NHS_ (B_ * S_ * HID_)
#define NWQ_ (HID_ * HID_)
#define NWKV_ (2 * NKV_ * HD_ * HID_)

__global__ void split4_kernel(const float* __restrict__ hs, const float* __restrict__ Wq,
                              const float* __restrict__ Wkv, const float* __restrict__ Wd)
{
    int t = blockIdx.x * blockDim.x + threadIdx.x;
    const int q0 = NHS_ / 4, q1 = q0 + NWQ_ / 4, q2 = q1 + NWKV_ / 4;
    const float* src;
    bf16 *dh, *dl;
    int i;
    if (t < q0)      { src = hs;  dh = g_hsh; dl = g_hsl; i = t * 4; }
    else if (t < q1) { src = Wq;  dh = g_wh;  dl = g_wl;  i = (t - q0) * 4; }
    else if (t < q2) { src = Wkv; dh = g_wh + NWQ_; dl = g_wl + NWQ_; i = (t - q1) * 4; }
    else             { src = Wd;  dh = g_wdh; dl = g_wdl; i = (t - q2) * 4; }
    float4 x = *(const float4*)(src + i);
    *(uint32_t*)(dh + i)     = packh(x.x, x.y);
    *(uint32_t*)(dh + i + 2) = packh(x.z, x.w);
    *(uint32_t*)(dl + i)     = packl(x.x, x.y);
    *(uint32_t*)(dl + i + 2) = packl(x.z, x.w);
}

// ---------------- NT GEMM: 512 threads, 128x256x32, bf16x3 de-chained --------
#define GBM 128
#define GBN 256
#define GBK 32
#define ARS 40
#define NSTG 3
#define AH_STG (GBM * ARS)
#define STGH ((2 * GBM + 2 * GBN) * ARS)
#define GSMEM (NSTG * STGH * 2)

__global__ __launch_bounds__(512, 1) void gemm_bf3(
    const bf16* __restrict__ Ah, const bf16* __restrict__ Al,
    const bf16* __restrict__ Wh, const bf16* __restrict__ Wl,
    const float* __restrict__ bias, float* __restrict__ C,
    int N, int K, int mode)
{
    extern __shared__ bf16 smh[];

    int tid = threadIdx.x, lane = tid & 31, wid = tid >> 5;
    int g = lane >> 2, tg = lane & 3;
    int wm = (wid & 3) << 5;
    int wn = (wid >> 2) << 6;
    int m0 = blockIdx.y * GBM, n0 = blockIdx.x * GBN;
    const bf16* Abh = Ah + (size_t)m0 * K;
    const bf16* Abl = Al + (size_t)m0 * K;
    const bf16* Bbh = Wh + (size_t)n0 * K;
    const bf16* Bbl = Wl + (size_t)n0 * K;

    float acc[2][8][4];
#pragma unroll
    for (int i = 0; i < 2; i++)
#pragma unroll
        for (int j = 0; j < 8; j++)
#pragma unroll
            for (int c = 0; c < 4; c++) acc[i][j][c] = 0.f;

    int nk = K / GBK;

    auto load_tile = [&](int kt, int s) {
        int k0 = kt * GBK;
        bf16* ah = smh + s * STGH;
        bf16* al = ah + AH_STG;
        bf16* bh = al + AH_STG;
        bf16* bl = bh + GBN * ARS;
        {
            int row = tid >> 2, q = tid & 3;
            size_t go = (size_t)row * K + k0 + q * 8;
            cp16(&ah[row * ARS + q * 8], Abh + go);
            cp16(&al[row * ARS + q * 8], Abl + go);
        }
#pragma unroll
        for (int i = 0; i < 2; i++) {
            int idx = tid + i * 512;
            int row = idx >> 2, q = idx & 3;
            size_t go = (size_t)row * K + k0 + q * 8;
            cp16(&bh[row * ARS + q * 8], Bbh + go);
            cp16(&bl[row * ARS + q * 8], Bbl + go);
        }
    };

    load_tile(0, 0); cp_commit();
    load_tile(1, 1); cp_commit();

    for (int kt = 0; kt < nk; kt++) {
        if (kt == nk - 1) cp_wait0(); else cp_wait1();
        __syncthreads();
        if (kt + 2 < nk) { load_tile(kt + 2, (kt + 2) % NSTG); cp_commit(); }

        int s = kt % NSTG;
        const bf16* ah = smh + s * STGH;
        const bf16* al = ah + AH_STG;
        const bf16* bh = al + AH_STG;
        const bf16* bl = bh + GBN * ARS;

#pragma unroll
        for (int k16 = 0; k16 < 2; k16++) {
            int kk = k16 * 16 + (lane >> 4) * 8;
            uint32_t fah[2][4], fal[2][4];
#pragma unroll
            for (int mi = 0; mi < 2; mi++) {
                int aoff = (wm + mi * 16 + (lane & 15)) * ARS + kk;
                ldsm4(fah[mi], ah + aoff);
                ldsm4(fal[mi], al + aoff);
            }
#pragma unroll
            for (int njp = 0; njp < 4; njp++) {
                int boff = (wn + njp * 16 + (lane & 15)) * ARS + kk;
                uint32_t fbh[4], fbl[4];
                ldsm4(fbh, bh + boff);
                ldsm4(fbl, bl + boff);
                // pass 1: hi*hi  (4 independent accumulators)
#pragma unroll
                for (int mi = 0; mi < 2; mi++) {
                    mma16(acc[mi][2 * njp],     fah[mi], fbh[0], fbh[2]);
                    mma16(acc[mi][2 * njp + 1], fah[mi], fbh[1], fbh[3]);
                }
                // pass 2: lo*hi
#pragma unroll
                for (int mi = 0; mi < 2; mi++) {
                    mma16(acc[mi][2 * njp],     fal[mi], fbh[0], fbh[2]);
                    mma16(acc[mi][2 * njp + 1], fal[mi], fbh[1], fbh[3]);
                }
                // pass 3: hi*lo
#pragma unroll
                for (int mi = 0; mi < 2; mi++) {
                    mma16(acc[mi][2 * njp],     fah[mi], fbl[0], fbl[2]);
                    mma16(acc[mi][2 * njp + 1], fah[mi], fbl[1], fbl[3]);
                }
            }
        }
    }

    // epilogue
#pragma unroll
    for (int mi = 0; mi < 2; mi++) {
#pragma unroll
        for (int nj = 0; nj < 8; nj++) {
            int col = n0 + wn + nj * 8 + tg * 2;
#pragma unroll
            for (int half = 0; half < 2; half++) {
                int row = m0 + wm + mi * 16 + g + half * 8;
                float v0 = acc[mi][nj][half * 2], v1 = acc[mi][nj][half * 2 + 1];
                if (mode == 0) {
                    C[(size_t)row * N + col]     = v0 + bias[col];
                    C[(size_t)row * N + col + 1] = v1 + bias[col + 1];
                } else {
                    int bb = row >> 11, s2 = row & (S_ - 1);
                    if (col < HID_) {
                        int hh = col >> 7, d = col & 127;
                        size_t o = (((size_t)bb * NH_ + hh) * S_ + s2) * HD_ + d;
                        g_qf[o] = v0; g_qf[o + 1] = v1;
                    } else {
                        int n2 = col - HID_;
                        int kh = n2 >> 8, cc = n2 & 255;
                        if (cc < 128) {
                            size_t o = (((size_t)bb * NKV_ + kh) * S_ + s2) * HD_ + cc;
                            g_kf[o] = v0; g_kf[o + 1] = v1;
                        } else {
                            int d = cc - 128;
                            size_t o = (((size_t)bb * NKV_ + kh) * S_ + s2) * HD_ + d;
                            *(uint32_t*)(g_vh + o) = packh(v0, v1);
                            *(uint32_t*)(g_vl + o) = packl(v0, v1);
                        }
                    }
                }
            }
        }
    }
}

// ---------------- RoPE + split ----------------
__global__ void rope_split(const float* __restrict__ cosT, const float* __restrict__ sinT)
{
    int idx = blockIdx.x * blockDim.x + threadIdx.x;
    int d = idx & 63;
    int r = idx >> 6;
    int s = r & (S_ - 1);
    int hh = r >> 11;
    float c1 = cosT[s * HD_ + d],      s1 = sinT[s * HD_ + d];
    float c2 = cosT[s * HD_ + d + 64], s2 = sinT[s * HD_ + d + 64];
    const float* p;
    bf16 *oh, *ol;
    if (hh < B_ * NH_) {
        p  = g_qf + (size_t)r * HD_;
        oh = g_qh + (size_t)r * HD_;
        ol = g_ql + (size_t)r * HD_;
    } else {
        size_t rr = (size_t)r - (size_t)B_ * NH_ * S_;
        p  = g_kf + rr * HD_;
        oh = g_kh + rr * HD_;
        ol = g_kl + rr * HD_;
    }
    float x1 = p[d], x2 = p[d + 64];
    sstore(oh, ol, d,      x1 * c1 - x2 * s1);
    sstore(oh, ol, d + 64, x2 * c2 + x1 * s2);
}

// ---------------- Flash attention, bf16x3 de-chained -------------------------
#define AQ 128
#define AK 64
#define RS_ 136
#define KVT (AK * RS_)
#define KVSTG (4 * KVT)
#define SBOFF (2 * AQ * RS_)
#define ASMEM ((SBOFF + 2 * KVSTG) * 2)

__global__ __launch_bounds__(256, 1) void attn_bf3()
{
    extern __shared__ bf16 smh[];
    bf16* Qh = smh;
    bf16* Ql = Qh + AQ * RS_;

    int qt = blockIdx.x, h = blockIdx.y, b = blockIdx.z;
    int tid = threadIdx.x, lane = tid & 31, wid = tid >> 5;
    int g = lane >> 2, tg = lane & 3;

    const bf16* Qbh = g_qh + (((size_t)b * NH_ + h) * S_ + (size_t)qt * AQ) * HD_;
    const bf16* Qbl = g_ql + (((size_t)b * NH_ + h) * S_ + (size_t)qt * AQ) * HD_;
    const bf16* Kbh = g_kh + ((size_t)b * NKV_ + (h >> 2)) * S_ * HD_;
    const bf16* Kbl = g_kl + ((size_t)b * NKV_ + (h >> 2)) * S_ * HD_;
    const bf16* Vbh = g_vh + ((size_t)b * NKV_ + (h >> 2)) * S_ * HD_;
    const bf16* Vbl = g_vl + ((size_t)b * NKV_ + (h >> 2)) * S_ * HD_;

#pragma unroll
    for (int i = 0; i < 8; i++) {
        int idx = tid + i * 256;
        int row = idx >> 4, q = idx & 15;
        size_t go = (size_t)row * HD_ + q * 8;
        cp16(&Qh[row * RS_ + q * 8], Qbh + go);
        cp16(&Ql[row * RS_ + q * 8], Qbl + go);
    }
    cp_commit();

    auto load_kv = [&](int kt, int s) {
        bf16* base = smh + SBOFF + s * KVSTG;
#pragma unroll
        for (int i = 0; i < 4; i++) {
            int idx = tid + i * 256;
            int row = idx >> 4, q = idx & 15;
            size_t go = (size_t)(kt * AK + row) * HD_ + q * 8;
            int so = row * RS_ + q * 8;
            cp16(&base[so],           Kbh + go);
            cp16(&base[KVT + so],     Kbl + go);
            cp16(&base[2 * KVT + so], Vbh + go);
            cp16(&base[3 * KVT + so], Vbl + go);
        }
    };

    float o[16][4];
#pragma unroll
    for (int j = 0; j < 16; j++)
#pragma unroll
        for (int c = 0; c < 4; c++) o[j][c] = 0.f;
    float m0 = -1e30f, m1 = -1e30f, l0 = 0.f, l1 = 0.f;
    const float scale = 0.08838834764831845f;
    int pr = wid * 16;

    int nkt = (qt + 1) * 2;
    load_kv(0, 0); cp_commit();

    for (int kt = 0; kt < nkt; kt++) {
        cp_wait0();
        __syncthreads();
        if (kt + 1 < nkt) { load_kv(kt + 1, (kt + 1) & 1); cp_commit(); }

        bf16* base = smh + SBOFF + (kt & 1) * KVSTG;
        bf16* Kh = base;
        bf16* Kl = base + KVT;
        bf16* Vh = base + 2 * KVT;
        bf16* Vl = base + 3 * KVT;

        float sf[8][4];
#pragma unroll
        for (int j = 0; j < 8; j++)
#pragma unroll
            for (int c = 0; c < 4; c++) sf[j][c] = 0.f;

        // S = Q K^T, de-chained: process 2 njp groups (4 accumulators) per pass set
#pragma unroll
        for (int k16 = 0; k16 < 8; k16++) {
            int kk = k16 * 16 + (lane >> 4) * 8;
            int aoff = (pr + (lane & 15)) * RS_ + kk;
            uint32_t fah[4], fal[4];
            ldsm4(fah, Qh + aoff);
            ldsm4(fal, Ql + aoff);
#pragma unroll
            for (int np2 = 0; np2 < 2; np2++) {
                uint32_t fbh[2][4], fbl[2][4];
#pragma unroll
                for (int u = 0; u < 2; u++) {
                    int boff = ((np2 * 2 + u) * 16 + (lane & 15)) * RS_ + kk;
                    ldsm4(fbh[u], Kh + boff);
                    ldsm4(fbl[u], Kl + boff);
                }
                // pass hh (4 independent accs)
#pragma unroll
                for (int u = 0; u < 2; u++) {
                    int j = (np2 * 2 + u) * 2;
                    mma16(sf[j],     fah, fbh[u][0], fbh[u][2]);
                    mma16(sf[j + 1], fah, fbh[u][1], fbh[u][3]);
                }
                // pass lh
#pragma unroll
                for (int u = 0; u < 2; u++) {
                    int j = (np2 * 2 + u) * 2;
                    mma16(sf[j],     fal, fbh[u][0], fbh[u][2]);
                    mma16(sf[j + 1], fal, fbh[u][1], fbh[u][3]);
                }
                // pass hl
#pragma unroll
                for (int u = 0; u < 2; u++) {
                    int j = (np2 * 2 + u) * 2;
                    mma16(sf[j],     fah, fbl[u][0], fbl[u][2]);
                    mma16(sf[j + 1], fah, fbl[u][1], fbl[u][3]);
                }
            }
        }

        int row0 = qt * AQ + wid * 16 + g;
        int colb = kt * AK + tg * 2;
        float mx0 = -1e30f, mx1 = -1e30f;
#pragma unroll
        for (int nj = 0; nj < 8; nj++) {
#pragma unroll
            for (int c = 0; c < 4; c++) {
                int col = colb + nj * 8 + (c & 1);
                int row = row0 + ((c & 2) ? 8 : 0);
                float v = sf[nj][c] * scale;
                if (col > row) v = -1e30f;
                sf[nj][c] = v;
                if (c < 2) mx0 = fmaxf(mx0, v); else mx1 = fmaxf(mx1, v);
            }
        }
        mx0 = fmaxf(mx0, __shfl_xor_sync(0xffffffffu, mx0, 1));
        mx0 = fmaxf(mx0, __shfl_xor_sync(0xffffffffu, mx0, 2));
        mx1 = fmaxf(mx1, __shfl_xor_sync(0xffffffffu, mx1, 1));
        mx1 = fmaxf(mx1, __shfl_xor_sync(0xffffffffu, mx1, 2));

        float mn0 = fmaxf(m0, mx0), mn1 = fmaxf(m1, mx1);
        float al0 = __expf(m0 - mn0), al1 = __expf(m1 - mn1);
        m0 = mn0; m1 = mn1;

        float rs0 = 0.f, rs1 = 0.f;
#pragma unroll
        for (int nj = 0; nj < 8; nj++) {
            float p0 = __expf(sf[nj][0] - mn0), p1 = __expf(sf[nj][1] - mn0);
            float p2 = __expf(sf[nj][2] - mn1), p3 = __expf(sf[nj][3] - mn1);
            sf[nj][0] = p0; sf[nj][1] = p1; sf[nj][2] = p2; sf[nj][3] = p3;
            rs0 += p0 + p1; rs1 += p2 + p3;
        }
        rs0 += __shfl_xor_sync(0xffffffffu, rs0, 1);
        rs0 += __shfl_xor_sync(0xffffffffu, rs0, 2);
        rs1 += __shfl_xor_sync(0xffffffffu, rs1, 1);
        rs1 += __shfl_xor_sync(0xffffffffu, rs1, 2);
        l0 = l0 * al0 + rs0;
        l1 = l1 * al1 + rs1;
#pragma unroll
        for (int j = 0; j < 16; j++) {
            o[j][0] *= al0; o[j][1] *= al0; o[j][2] *= al1; o[j][3] *= al1;
        }

        // O += P @ V, de-chained: per t process 2 dj (4 accumulators) per pass set
#pragma unroll
        for (int t = 0; t < 4; t++) {
            uint32_t pah[4], pal[4];
            pah[0] = packh(sf[2 * t][0], sf[2 * t][1]);
            pal[0] = packl(sf[2 * t][0], sf[2 * t][1]);
            pah[1] = packh(sf[2 * t][2], sf[2 * t][3]);
            pal[1] = packl(sf[2 * t][2], sf[2 * t][3]);
            pah[2] = packh(sf[2 * t + 1][0], sf[2 * t + 1][1]);
            pal[2] = packl(sf[2 * t + 1][0], sf[2 * t + 1][1]);
            pah[3] = packh(sf[2 * t + 1][2], sf[2 * t + 1][3]);
            pal[3] = packl(sf[2 * t + 1][2], sf[2 * t + 1][3]);
#pragma unroll
            for (int dp = 0; dp < 4; dp++) {
                uint32_t fvh[2][4], fvl[2][4];
#pragma unroll
                for (int u = 0; u < 2; u++) {
                    int dj = dp * 2 + u;
                    int voff = (t * 16 + (lane & 15)) * RS_ + dj * 16 + (lane >> 4) * 8;
                    ldsm4t(fvh[u], Vh + voff);
                    ldsm4t(fvl[u], Vl + voff);
                }
                // pass hh
#pragma unroll
                for (int u = 0; u < 2; u++) {
                    int dj = dp * 2 + u;
                    mma16(o[2 * dj],     pah, fvh[u][0], fvh[u][1]);
                    mma16(o[2 * dj + 1], pah, fvh[u][2], fvh[u][3]);
                }
                // pass lh
#pragma unroll
                for (int u = 0; u < 2; u++) {
                    int dj = dp * 2 + u;
                    mma16(o[2 * dj],     pal, fvh[u][0], fvh[u][1]);
                    mma16(o[2 * dj + 1], pal, fvh[u][2], fvh[u][3]);
                }
                // pass hl
#pragma unroll
                for (int u = 0; u < 2; u++) {
                    int dj = dp * 2 + u;
                    mma16(o[2 * dj],     pah, fvl[u][0], fvl[u][1]);
                    mma16(o[2 * dj + 1], pah, fvl[u][2], fvl[u][3]);
                }
            }
        }
    }

    float il0 = 1.f / l0, il1 = 1.f / l1;
    int row0 = qt * AQ + wid * 16 + g;
    size_t b0 = ((size_t)b * S_ + row0) * HID_ + (size_t)h * HD_;
    size_t b1 = b0 + (size_t)8 * HID_;
#pragma unroll
    for (int nj = 0; nj < 16; nj++) {
        int d = nj * 8 + tg * 2;
        float v0 = o[nj][0] * il0, v1 = o[nj][1] * il0;
        *(uint32_t*)(g_ch + b0 + d) = packh(v0, v1);
        *(uint32_t*)(g_cl + b0 + d) = packl(v0, v1);
        float w0 = o[nj][2] * il1, w1 = o[nj][3] * il1;
        *(uint32_t*)(g_ch + b1 + d) = packh(w0, w1);
        *(uint32_t*)(g_cl + b1 + d) = packl(w0, w1);
    }
}

// ---------------- launch ----------------
extern "C" void kernel_launch(void* const* d_in, const int* in_sizes, int n_in,
                              void* d_out, int out_size)
{
    const float* hs   = (const float*)d_in[0];
    const float* cosT = (const float*)d_in[2];
    const float* sinT = (const float*)d_in[3];
    const float* Wq   = (const float*)d_in[4];
    const float* Wkv  = (const float*)d_in[5];
    const float* Wd   = (const float*)d_in[6];
    const float* bd   = (const float*)d_in[7];
    float* out = (float*)d_out;

    cudaFuncSetAttribute(gemm_bf3, cudaFuncAttributeMaxDynamicSharedMemorySize, GSMEM);
    cudaFuncSetAttribute(attn_bf3, cudaFuncAttributeMaxDynamicSharedMemorySize, ASMEM);

    void *hsh, *hsl, *wh, *wl, *wdh, *wdl, *ch, *cl;
    cudaGetSymbolAddress(&hsh, g_hsh);  cudaGetSymbolAddress(&hsl, g_hsl);
    cudaGetSymbolAddress(&wh,  g_wh);   cudaGetSymbolAddress(&wl,  g_wl);
    cudaGetSymbolAddress(&wdh, g_wdh);  cudaGetSymbolAddress(&wdl, g_wdl);
    cudaGetSymbolAddress(&ch,  g_ch);   cudaGetSymbolAddress(&cl,  g_cl);

    const int total4 = (NHS_ + NWQ_ + NWKV_ + NWQ_) / 4;
    split4_kernel<<<total4 / 256, 256>>>(hs, Wq, Wkv, Wd);

    gemm_bf3<<<dim3((HID_ + 2 * NKV_ * HD_) / GBN, (B_ * S_) / GBM), 512, GSMEM>>>(
        (const bf16*)hsh, (const bf16*)hsl, (const bf16*)wh, (const bf16*)wl,
        bd, out, HID_ + 2 * NKV_ * HD_, HID_, 1);

    rope_split<<<(B_ * (NH_ + NKV_) * S_ * 64) / 256, 256>>>(cosT, sinT);

    attn_bf3<<<dim3(S_ / AQ, NH_, B_), 256, ASMEM>>>();

    gemm_bf3<<<dim3(HID_ / GBN, (B_ * S_) / GBM), 512, GSMEM>>>(
        (const bf16*)ch, (const bf16*)cl, (const bf16*)wdh, (const bf16*)wdl,
        bd, out, HID_, HID_, 0);
}

// round 8
// speedup vs baseline: 1.3677x; 1.3677x over previous
#include <cuda_runtime.h>
#include <cuda_bf16.h>
#include <cuda_fp16.h>
#include <cstdint>

#define B_   2
#define S_   2048
#define HID_ 4096
#define NH_  32
#define NKV_ 8
#define HD_  128

typedef __nv_bfloat16 bf16;
typedef __half f16;

// ---------------- device scratch ----------------
__device__ f16   g_hsh[(size_t)B_ * S_ * HID_];
__device__ f16   g_hsl[(size_t)B_ * S_ * HID_];
__device__ f16   g_w  [(size_t)(HID_ + 2 * NKV_ * HD_) * HID_];
__device__ f16   g_wd [(size_t)HID_ * HID_];
__device__ float g_qf [(size_t)B_ * NH_ * S_ * HD_];
__device__ float g_kf [(size_t)B_ * NKV_ * S_ * HD_];
__device__ bf16  g_qh [(size_t)B_ * NH_ * S_ * HD_];
__device__ bf16  g_ql [(size_t)B_ * NH_ * S_ * HD_];
__device__ bf16  g_kh [(size_t)B_ * NKV_ * S_ * HD_];
__device__ bf16  g_kl [(size_t)B_ * NKV_ * S_ * HD_];
__device__ bf16  g_vh [(size_t)B_ * NKV_ * S_ * HD_];
__device__ bf16  g_vl [(size_t)B_ * NKV_ * S_ * HD_];
__device__ f16   g_ch [(size_t)B_ * S_ * HID_];
__device__ f16   g_cl [(size_t)B_ * S_ * HID_];

// ---------------- helpers ----------------
__device__ __forceinline__ void cp16(void* dst, const void* src) {
    unsigned d = (unsigned)__cvta_generic_to_shared(dst);
    asm volatile("cp.async.cg.shared.global [%0], [%1], 16;\n" :: "r"(d), "l"(src));
}
__device__ __forceinline__ void cp_commit() { asm volatile("cp.async.commit_group;\n"); }
__device__ __forceinline__ void cp_wait0()  { asm volatile("cp.async.wait_group 0;\n"); }
__device__ __forceinline__ void cp_wait1()  { asm volatile("cp.async.wait_group 1;\n"); }

__device__ __forceinline__ void ldsm4(uint32_t* r, const void* p) {
    uint32_t a = (uint32_t)__cvta_generic_to_shared(p);
    asm volatile("ldmatrix.sync.aligned.m8n8.x4.shared.b16 {%0,%1,%2,%3}, [%4];\n"
        : "=r"(r[0]), "=r"(r[1]), "=r"(r[2]), "=r"(r[3]) : "r"(a));
}
__device__ __forceinline__ void ldsm4t(uint32_t* r, const void* p) {
    uint32_t a = (uint32_t)__cvta_generic_to_shared(p);
    asm volatile("ldmatrix.sync.aligned.m8n8.x4.trans.shared.b16 {%0,%1,%2,%3}, [%4];\n"
        : "=r"(r[0]), "=r"(r[1]), "=r"(r[2]), "=r"(r[3]) : "r"(a));
}

// bf16 mma (attention)
__device__ __forceinline__ void mma16(float* c, const uint32_t* a, uint32_t b0, uint32_t b1) {
    asm volatile(
        "mma.sync.aligned.m16n8k16.row.col.f32.bf16.bf16.f32 "
        "{%0,%1,%2,%3},{%4,%5,%6,%7},{%8,%9},{%0,%1,%2,%3};\n"
        : "+f"(c[0]), "+f"(c[1]), "+f"(c[2]), "+f"(c[3])
        : "r"(a[0]), "r"(a[1]), "r"(a[2]), "r"(a[3]), "r"(b0), "r"(b1));
}
// fp16 mma (GEMMs)
__device__ __forceinline__ void mma16h(float* c, const uint32_t* a, uint32_t b0, uint32_t b1) {
    asm volatile(
        "mma.sync.aligned.m16n8k16.row.col.f32.f16.f16.f32 "
        "{%0,%1,%2,%3},{%4,%5,%6,%7},{%8,%9},{%0,%1,%2,%3};\n"
        : "+f"(c[0]), "+f"(c[1]), "+f"(c[2]), "+f"(c[3])
        : "r"(a[0]), "r"(a[1]), "r"(a[2]), "r"(a[3]), "r"(b0), "r"(b1));
}

// bf16 packing (attention path)
__device__ __forceinline__ uint32_t packh(float e, float o) {
    __nv_bfloat162 t = __floats2bfloat162_rn(e, o);
    return *reinterpret_cast<const uint32_t*>(&t);
}
__device__ __forceinline__ uint32_t packl(float e, float o) {
    float he = __bfloat162float(__float2bfloat16_rn(e));
    float ho = __bfloat162float(__float2bfloat16_rn(o));
    return packh(e - he, o - ho);
}
__device__ __forceinline__ void sstore(bf16* oh, bf16* ol, int i, float v) {
    bf16 h = __float2bfloat16_rn(v);
    oh[i] = h;
    ol[i] = __float2bfloat16_rn(v - __bfloat162float(h));
}
// fp16 packing (GEMM path)
__device__ __forceinline__ uint32_t packh16(float e, float o) {
    __half2 t = __floats2half2_rn(e, o);
    return *reinterpret_cast<const uint32_t*>(&t);
}
__device__ __forceinline__ uint32_t packl16(float e, float o) {
    float he = __half2float(__float2half_rn(e));
    float ho = __half2float(__float2half_rn(o));
    return packh16(e - he, o - ho);
}

// ---------------- fused split pass ----------
#define NHS_ (B_ * S_ * HID_)
#define NWQ_ (HID_ * HID_)
#define NWKV_ (2 * NKV_ * HD_ * HID_)

__global__ void split4_kernel(const float* __restrict__ hs, const float* __restrict__ Wq,
                              const float* __restrict__ Wkv, const float* __restrict__ Wd)
{
    int t = blockIdx.x * blockDim.x + threadIdx.x;
    const int q0 = NHS_ / 4, q1 = q0 + NWQ_ / 4, q2 = q1 + NWKV_ / 4;
    if (t < q0) {
        int i = t * 4;
        float4 x = *(const float4*)(hs + i);
        *(uint32_t*)(g_hsh + i)     = packh16(x.x, x.y);
        *(uint32_t*)(g_hsh + i + 2) = packh16(x.z, x.w);
        *(uint32_t*)(g_hsl + i)     = packl16(x.x, x.y);
        *(uint32_t*)(g_hsl + i + 2) = packl16(x.z, x.w);
    } else {
        const float* src;
        f16* dst;
        int i;
        if (t < q1)      { src = Wq;  dst = g_w;         i = (t - q0) * 4; }
        else if (t < q2) { src = Wkv; dst = g_w + NWQ_;  i = (t - q1) * 4; }
        else             { src = Wd;  dst = g_wd;        i = (t - q2) * 4; }
        float4 x = *(const float4*)(src + i);
        *(uint32_t*)(dst + i)     = packh16(x.x, x.y);
        *(uint32_t*)(dst + i + 2) = packh16(x.z, x.w);
    }
}

// ------------- NT GEMM: 512 thr, 128x256x32, fp16 A-split x2, 3-stage --------
#define GBM 128
#define GBN 256
#define GBK 32
#define ARS 40
#define NSTG 3
#define AH_STG (GBM * ARS)                 // 5120 halves
#define STGH ((2 * GBM + GBN) * ARS)       // 20480 halves per stage
#define GSMEM (NSTG * STGH * 2)            // 122880 bytes

__global__ __launch_bounds__(512, 1) void gemm_f16x2(
    const f16* __restrict__ Ah, const f16* __restrict__ Al,
    const f16* __restrict__ Wh,
    const float* __restrict__ bias, float* __restrict__ C,
    int N, int K, int mode)
{
    extern __shared__ f16 smh[];

    int tid = threadIdx.x, lane = tid & 31, wid = tid >> 5;
    int g = lane >> 2, tg = lane & 3;
    int wm = (wid & 3) << 5;
    int wn = (wid >> 2) << 6;
    int m0 = blockIdx.y * GBM, n0 = blockIdx.x * GBN;
    const f16* Abh = Ah + (size_t)m0 * K;
    const f16* Abl = Al + (size_t)m0 * K;
    const f16* Bbh = Wh + (size_t)n0 * K;

    float acc[2][8][4];
#pragma unroll
    for (int i = 0; i < 2; i++)
#pragma unroll
        for (int j = 0; j < 8; j++)
#pragma unroll
            for (int c = 0; c < 4; c++) acc[i][j][c] = 0.f;

    int nk = K / GBK;

    auto load_tile = [&](int kt, int s) {
        int k0 = kt * GBK;
        f16* ah = smh + s * STGH;
        f16* al = ah + AH_STG;
        f16* bh = al + AH_STG;
        {   // A hi+lo: 512 (row,q) slots, each thread does both arrays
            int row = tid >> 2, q = tid & 3;
            size_t go = (size_t)row * K + k0 + q * 8;
            cp16(&ah[row * ARS + q * 8], Abh + go);
            cp16(&al[row * ARS + q * 8], Abl + go);
        }
#pragma unroll
        for (int i = 0; i < 2; i++) {   // B: 1024 slots
            int idx = tid + i * 512;
            int row = idx >> 2, q = idx & 3;
            size_t go = (size_t)row * K + k0 + q * 8;
            cp16(&bh[row * ARS + q * 8], Bbh + go);
        }
    };

    load_tile(0, 0); cp_commit();
    load_tile(1, 1); cp_commit();

    for (int kt = 0; kt < nk; kt++) {
        if (kt == nk - 1) cp_wait0(); else cp_wait1();
        __syncthreads();
        if (kt + 2 < nk) { load_tile(kt + 2, (kt + 2) % NSTG); cp_commit(); }

        int s = kt % NSTG;
        const f16* ah = smh + s * STGH;
        const f16* al = ah + AH_STG;
        const f16* bh = al + AH_STG;

#pragma unroll
        for (int k16 = 0; k16 < 2; k16++) {
            int kk = k16 * 16 + (lane >> 4) * 8;
            uint32_t fah[2][4], fal[2][4];
#pragma unroll
            for (int mi = 0; mi < 2; mi++) {
                int aoff = (wm + mi * 16 + (lane & 15)) * ARS + kk;
                ldsm4(fah[mi], ah + aoff);
                ldsm4(fal[mi], al + aoff);
            }
#pragma unroll
            for (int njp = 0; njp < 4; njp++) {
                int boff = (wn + njp * 16 + (lane & 15)) * ARS + kk;
                uint32_t fbh[4];
                ldsm4(fbh, bh + boff);
                // pass 1: a_hi * b   (4 independent accumulators)
#pragma unroll
                for (int mi = 0; mi < 2; mi++) {
                    mma16h(acc[mi][2 * njp],     fah[mi], fbh[0], fbh[2]);
                    mma16h(acc[mi][2 * njp + 1], fah[mi], fbh[1], fbh[3]);
                }
                // pass 2: a_lo * b
#pragma unroll
                for (int mi = 0; mi < 2; mi++) {
                    mma16h(acc[mi][2 * njp],     fal[mi], fbh[0], fbh[2]);
                    mma16h(acc[mi][2 * njp + 1], fal[mi], fbh[1], fbh[3]);
                }
            }
        }
    }

    // epilogue
#pragma unroll
    for (int mi = 0; mi < 2; mi++) {
#pragma unroll
        for (int nj = 0; nj < 8; nj++) {
            int col = n0 + wn + nj * 8 + tg * 2;
#pragma unroll
            for (int half = 0; half < 2; half++) {
                int row = m0 + wm + mi * 16 + g + half * 8;
                float v0 = acc[mi][nj][half * 2], v1 = acc[mi][nj][half * 2 + 1];
                if (mode == 0) {
                    C[(size_t)row * N + col]     = v0 + bias[col];
                    C[(size_t)row * N + col + 1] = v1 + bias[col + 1];
                } else {
                    int bb = row >> 11, s2 = row & (S_ - 1);
                    if (col < HID_) {
                        int hh = col >> 7, d = col & 127;
                        size_t o = (((size_t)bb * NH_ + hh) * S_ + s2) * HD_ + d;
                        g_qf[o] = v0; g_qf[o + 1] = v1;
                    } else {
                        int n2 = col - HID_;
                        int kh = n2 >> 8, cc = n2 & 255;
                        if (cc < 128) {
                            size_t o = (((size_t)bb * NKV_ + kh) * S_ + s2) * HD_ + cc;
                            g_kf[o] = v0; g_kf[o + 1] = v1;
                        } else {
                            int d = cc - 128;
                            size_t o = (((size_t)bb * NKV_ + kh) * S_ + s2) * HD_ + d;
                            *(uint32_t*)(g_vh + o) = packh(v0, v1);
                            *(uint32_t*)(g_vl + o) = packl(v0, v1);
                        }
                    }
                }
            }
        }
    }
}

// ---------------- RoPE + split (fp32 -> bf16 hi/lo) ----------------
__global__ void rope_split(const float* __restrict__ cosT, const float* __restrict__ sinT)
{
    int idx = blockIdx.x * blockDim.x + threadIdx.x;
    int d = idx & 63;
    int r = idx >> 6;
    int s = r & (S_ - 1);
    int hh = r >> 11;
    float c1 = cosT[s * HD_ + d],      s1 = sinT[s * HD_ + d];
    float c2 = cosT[s * HD_ + d + 64], s2 = sinT[s * HD_ + d + 64];
    const float* p;
    bf16 *oh, *ol;
    if (hh < B_ * NH_) {
        p  = g_qf + (size_t)r * HD_;
        oh = g_qh + (size_t)r * HD_;
        ol = g_ql + (size_t)r * HD_;
    } else {
        size_t rr = (size_t)r - (size_t)B_ * NH_ * S_;
        p  = g_kf + rr * HD_;
        oh = g_kh + rr * HD_;
        ol = g_kl + rr * HD_;
    }
    float x1 = p[d], x2 = p[d + 64];
    sstore(oh, ol, d,      x1 * c1 - x2 * s1);
    sstore(oh, ol, d + 64, x2 * c2 + x1 * s2);
}

// ---------------- Flash attention, bf16x3 (unchanged math) -------------------
#define AQ 128
#define AK 64
#define RS_ 136
#define KVT (AK * RS_)
#define KVSTG (4 * KVT)
#define SBOFF (2 * AQ * RS_)
#define ASMEM ((SBOFF + 2 * KVSTG) * 2)

__global__ __launch_bounds__(256, 1) void attn_bf3()
{
    extern __shared__ bf16 smb[];
    bf16* Qh = smb;
    bf16* Ql = Qh + AQ * RS_;

    int qt = gridDim.x - 1 - blockIdx.x;   // heaviest causal tiles first
    int h = blockIdx.y, b = blockIdx.z;
    int tid = threadIdx.x, lane = tid & 31, wid = tid >> 5;
    int g = lane >> 2, tg = lane & 3;

    const bf16* Qbh = g_qh + (((size_t)b * NH_ + h) * S_ + (size_t)qt * AQ) * HD_;
    const bf16* Qbl = g_ql + (((size_t)b * NH_ + h) * S_ + (size_t)qt * AQ) * HD_;
    const bf16* Kbh = g_kh + ((size_t)b * NKV_ + (h >> 2)) * S_ * HD_;
    const bf16* Kbl = g_kl + ((size_t)b * NKV_ + (h >> 2)) * S_ * HD_;
    const bf16* Vbh = g_vh + ((size_t)b * NKV_ + (h >> 2)) * S_ * HD_;
    const bf16* Vbl = g_vl + ((size_t)b * NKV_ + (h >> 2)) * S_ * HD_;

#pragma unroll
    for (int i = 0; i < 8; i++) {
        int idx = tid + i * 256;
        int row = idx >> 4, q = idx & 15;
        size_t go = (size_t)row * HD_ + q * 8;
        cp16(&Qh[row * RS_ + q * 8], Qbh + go);
        cp16(&Ql[row * RS_ + q * 8], Qbl + go);
    }
    cp_commit();

    auto load_kv = [&](int kt, int s) {
        bf16* base = smb + SBOFF + s * KVSTG;
#pragma unroll
        for (int i = 0; i < 4; i++) {
            int idx = tid + i * 256;
            int row = idx >> 4, q = idx & 15;
            size_t go = (size_t)(kt * AK + row) * HD_ + q * 8;
            int so = row * RS_ + q * 8;
            cp16(&base[so],           Kbh + go);
            cp16(&base[KVT + so],     Kbl + go);
            cp16(&base[2 * KVT + so], Vbh + go);
            cp16(&base[3 * KVT + so], Vbl + go);
        }
    };

    float o[16][4];
#pragma unroll
    for (int j = 0; j < 16; j++)
#pragma unroll
        for (int c = 0; c < 4; c++) o[j][c] = 0.f;
    float m0 = -1e30f, m1 = -1e30f, l0 = 0.f, l1 = 0.f;
    const float scale = 0.08838834764831845f;
    int pr = wid * 16;

    int nkt = (qt + 1) * 2;
    load_kv(0, 0); cp_commit();

    for (int kt = 0; kt < nkt; kt++) {
        cp_wait0();
        __syncthreads();
        if (kt + 1 < nkt) { load_kv(kt + 1, (kt + 1) & 1); cp_commit(); }

        bf16* base = smb + SBOFF + (kt & 1) * KVSTG;
        bf16* Kh = base;
        bf16* Kl = base + KVT;
        bf16* Vh = base + 2 * KVT;
        bf16* Vl = base + 3 * KVT;

        float sf[8][4];
#pragma unroll
        for (int j = 0; j < 8; j++)
#pragma unroll
            for (int c = 0; c < 4; c++) sf[j][c] = 0.f;

#pragma unroll
        for (int k16 = 0; k16 < 8; k16++) {
            int kk = k16 * 16 + (lane >> 4) * 8;
            int aoff = (pr + (lane & 15)) * RS_ + kk;
            uint32_t fah[4], fal[4];
            ldsm4(fah, Qh + aoff);
            ldsm4(fal, Ql + aoff);
#pragma unroll
            for (int np2 = 0; np2 < 2; np2++) {
                uint32_t fbh[2][4], fbl[2][4];
#pragma unroll
                for (int u = 0; u < 2; u++) {
                    int boff = ((np2 * 2 + u) * 16 + (lane & 15)) * RS_ + kk;
                    ldsm4(fbh[u], Kh + boff);
                    ldsm4(fbl[u], Kl + boff);
                }
#pragma unroll
                for (int u = 0; u < 2; u++) {
                    int j = (np2 * 2 + u) * 2;
                    mma16(sf[j],     fah, fbh[u][0], fbh[u][2]);
                    mma16(sf[j + 1], fah, fbh[u][1], fbh[u][3]);
                }
#pragma unroll
                for (int u = 0; u < 2; u++) {
                    int j = (np2 * 2 + u) * 2;
                    mma16(sf[j],     fal, fbh[u][0], fbh[u][2]);
                    mma16(sf[j + 1], fal, fbh[u][1], fbh[u][3]);
                }
#pragma unroll
                for (int u = 0; u < 2; u++) {
                    int j = (np2 * 2 + u) * 2;
                    mma16(sf[j],     fah, fbl[u][0], fbl[u][2]);
                    mma16(sf[j + 1], fah, fbl[u][1], fbl[u][3]);
                }
            }
        }

        int row0 = qt * AQ + wid * 16 + g;
        int colb = kt * AK + tg * 2;
        float mx0 = -1e30f, mx1 = -1e30f;
#pragma unroll
        for (int nj = 0; nj < 8; nj++) {
#pragma unroll
            for (int c = 0; c < 4; c++) {
                int col = colb + nj * 8 + (c & 1);
                int row = row0 + ((c & 2) ? 8 : 0);
                float v = sf[nj][c] * scale;
                if (col > row) v = -1e30f;
                sf[nj][c] = v;
                if (c < 2) mx0 = fmaxf(mx0, v); else mx1 = fmaxf(mx1, v);
            }
        }
        mx0 = fmaxf(mx0, __shfl_xor_sync(0xffffffffu, mx0, 1));
        mx0 = fmaxf(mx0, __shfl_xor_sync(0xffffffffu, mx0, 2));
        mx1 = fmaxf(mx1, __shfl_xor_sync(0xffffffffu, mx1, 1));
        mx1 = fmaxf(mx1, __shfl_xor_sync(0xffffffffu, mx1, 2));

        float mn0 = fmaxf(m0, mx0), mn1 = fmaxf(m1, mx1);
        float al0 = __expf(m0 - mn0), al1 = __expf(m1 - mn1);
        m0 = mn0; m1 = mn1;

        float rs0 = 0.f, rs1 = 0.f;
#pragma unroll
        for (int nj = 0; nj < 8; nj++) {
            float p0 = __expf(sf[nj][0] - mn0), p1 = __expf(sf[nj][1] - mn0);
            float p2 = __expf(sf[nj][2] - mn1), p3 = __expf(sf[nj][3] - mn1);
            sf[nj][0] = p0; sf[nj][1] = p1; sf[nj][2] = p2; sf[nj][3] = p3;
            rs0 += p0 + p1; rs1 += p2 + p3;
        }
        rs0 += __shfl_xor_sync(0xffffffffu, rs0, 1);
        rs0 += __shfl_xor_sync(0xffffffffu, rs0, 2);
        rs1 += __shfl_xor_sync(0xffffffffu, rs1, 1);
        rs1 += __shfl_xor_sync(0xffffffffu, rs1, 2);
        l0 = l0 * al0 + rs0;
        l1 = l1 * al1 + rs1;
#pragma unroll
        for (int j = 0; j < 16; j++) {
            o[j][0] *= al0; o[j][1] *= al0; o[j][2] *= al1; o[j][3] *= al1;
        }

#pragma unroll
        for (int t = 0; t < 4; t++) {
            uint32_t pah[4], pal[4];
            pah[0] = packh(sf[2 * t][0], sf[2 * t][1]);
            pal[0] = packl(sf[2 * t][0], sf[2 * t][1]);
            pah[1] = packh(sf[2 * t][2], sf[2 * t][3]);
            pal[1] = packl(sf[2 * t][2], sf[2 * t][3]);
            pah[2] = packh(sf[2 * t + 1][0], sf[2 * t + 1][1]);
            pal[2] = packl(sf[2 * t + 1][0], sf[2 * t + 1][1]);
            pah[3] = packh(sf[2 * t + 1][2], sf[2 * t + 1][3]);
            pal[3] = packl(sf[2 * t + 1][2], sf[2 * t + 1][3]);
#pragma unroll
            for (int dp = 0; dp < 4; dp++) {
                uint32_t fvh[2][4], fvl[2][4];
#pragma unroll
                for (int u = 0; u < 2; u++) {
                    int dj = dp * 2 + u;
                    int voff = (t * 16 + (lane & 15)) * RS_ + dj * 16 + (lane >> 4) * 8;
                    ldsm4t(fvh[u], Vh + voff);
                    ldsm4t(fvl[u], Vl + voff);
                }
#pragma unroll
                for (int u = 0; u < 2; u++) {
                    int dj = dp * 2 + u;
                    mma16(o[2 * dj],     pah, fvh[u][0], fvh[u][1]);
                    mma16(o[2 * dj + 1], pah, fvh[u][2], fvh[u][3]);
                }
#pragma unroll
                for (int u = 0; u < 2; u++) {
                    int dj = dp * 2 + u;
                    mma16(o[2 * dj],     pal, fvh[u][0], fvh[u][1]);
                    mma16(o[2 * dj + 1], pal, fvh[u][2], fvh[u][3]);
                }
#pragma unroll
                for (int u = 0; u < 2; u++) {
                    int dj = dp * 2 + u;
                    mma16(o[2 * dj],     pah, fvl[u][0], fvl[u][1]);
                    mma16(o[2 * dj + 1], pah, fvl[u][2], fvl[u][3]);
                }
            }
        }
    }

    // epilogue: O/l -> ctx split to fp16 hi/lo (GEMM2 A-operand)
    float il0 = 1.f / l0, il1 = 1.f / l1;
    int row0 = qt * AQ + wid * 16 + g;
    size_t b0 = ((size_t)b * S_ + row0) * HID_ + (size_t)h * HD_;
    size_t b1 = b0 + (size_t)8 * HID_;
#pragma unroll
    for (int nj = 0; nj < 16; nj++) {
        int d = nj * 8 + tg * 2;
        float v0 = o[nj][0] * il0, v1 = o[nj][1] * il0;
        *(uint32_t*)(g_ch + b0 + d) = packh16(v0, v1);
        *(uint32_t*)(g_cl + b0 + d) = packl16(v0, v1);
        float w0 = o[nj][2] * il1, w1 = o[nj][3] * il1;
        *(uint32_t*)(g_ch + b1 + d) = packh16(w0, w1);
        *(uint32_t*)(g_cl + b1 + d) = packl16(w0, w1);
    }
}

// ---------------- launch ----------------
extern "C" void kernel_launch(void* const* d_in, const int* in_sizes, int n_in,
                              void* d_out, int out_size)
{
    const float* hs   = (const float*)d_in[0];
    const float* cosT = (const float*)d_in[2];
    const float* sinT = (const float*)d_in[3];
    const float* Wq   = (const float*)d_in[4];
    const float* Wkv  = (const float*)d_in[5];
    const float* Wd   = (const float*)d_in[6];
    const float* bd   = (const float*)d_in[7];
    float* out = (float*)d_out;

    cudaFuncSetAttribute(gemm_f16x2, cudaFuncAttributeMaxDynamicSharedMemorySize, GSMEM);
    cudaFuncSetAttribute(attn_bf3, cudaFuncAttributeMaxDynamicSharedMemorySize, ASMEM);

    void *hsh, *hsl, *w, *wd, *ch, *cl;
    cudaGetSymbolAddress(&hsh, g_hsh);  cudaGetSymbolAddress(&hsl, g_hsl);
    cudaGetSymbolAddress(&w,   g_w);    cudaGetSymbolAddress(&wd,  g_wd);
    cudaGetSymbolAddress(&ch,  g_ch);   cudaGetSymbolAddress(&cl,  g_cl);

    const int total4 = (NHS_ + NWQ_ + NWKV_ + NWQ_) / 4;
    split4_kernel<<<total4 / 256, 256>>>(hs, Wq, Wkv, Wd);

    gemm_f16x2<<<dim3((HID_ + 2 * NKV_ * HD_) / GBN, (B_ * S_) / GBM), 512, GSMEM>>>(
        (const f16*)hsh, (const f16*)hsl, (const f16*)w,
        bd, out, HID_ + 2 * NKV_ * HD_, HID_, 1);

    rope_split<<<(B_ * (NH_ + NKV_) * S_ * 64) / 256, 256>>>(cosT, sinT);

    attn_bf3<<<dim3(S_ / AQ, NH_, B_), 256, ASMEM>>>();

    gemm_f16x2<<<dim3(HID_ / GBN, (B_ * S_) / GBM), 512, GSMEM>>>(
        (const f16*)ch, (const f16*)cl, (const f16*)wd,
        bd, out, HID_, HID_, 0);
}

// round 9
// speedup vs baseline: 1.4696x; 1.0745x over previous
#include <cuda_runtime.h>
#include <cuda_fp16.h>
#include <cstdint>

#define B_   2
#define S_   2048
#define HID_ 4096
#define NH_  32
#define NKV_ 8
#define HD_  128

typedef __half f16;

// ---------------- device scratch ----------------
__device__ f16   g_hsh[(size_t)B_ * S_ * HID_];
__device__ f16   g_hsl[(size_t)B_ * S_ * HID_];
__device__ f16   g_w  [(size_t)(HID_ + 2 * NKV_ * HD_) * HID_];
__device__ f16   g_wd [(size_t)HID_ * HID_];
__device__ float g_qf [(size_t)B_ * NH_ * S_ * HD_];
__device__ float g_kf [(size_t)B_ * NKV_ * S_ * HD_];
__device__ f16   g_qh [(size_t)B_ * NH_ * S_ * HD_];
__device__ f16   g_ql [(size_t)B_ * NH_ * S_ * HD_];
__device__ f16   g_kh [(size_t)B_ * NKV_ * S_ * HD_];
__device__ f16   g_vh [(size_t)B_ * NKV_ * S_ * HD_];
__device__ f16   g_ch [(size_t)B_ * S_ * HID_];
__device__ f16   g_cl [(size_t)B_ * S_ * HID_];

// ---------------- helpers ----------------
__device__ __forceinline__ void cp16(void* dst, const void* src) {
    unsigned d = (unsigned)__cvta_generic_to_shared(dst);
    asm volatile("cp.async.cg.shared.global [%0], [%1], 16;\n" :: "r"(d), "l"(src));
}
__device__ __forceinline__ void cp_commit() { asm volatile("cp.async.commit_group;\n"); }
__device__ __forceinline__ void cp_wait0()  { asm volatile("cp.async.wait_group 0;\n"); }
__device__ __forceinline__ void cp_wait1()  { asm volatile("cp.async.wait_group 1;\n"); }

__device__ __forceinline__ void ldsm4(uint32_t* r, const void* p) {
    uint32_t a = (uint32_t)__cvta_generic_to_shared(p);
    asm volatile("ldmatrix.sync.aligned.m8n8.x4.shared.b16 {%0,%1,%2,%3}, [%4];\n"
        : "=r"(r[0]), "=r"(r[1]), "=r"(r[2]), "=r"(r[3]) : "r"(a));
}
__device__ __forceinline__ void ldsm4t(uint32_t* r, const void* p) {
    uint32_t a = (uint32_t)__cvta_generic_to_shared(p);
    asm volatile("ldmatrix.sync.aligned.m8n8.x4.trans.shared.b16 {%0,%1,%2,%3}, [%4];\n"
        : "=r"(r[0]), "=r"(r[1]), "=r"(r[2]), "=r"(r[3]) : "r"(a));
}

// fp16 mma, fp32 accumulate
__device__ __forceinline__ void mma16h(float* c, const uint32_t* a, uint32_t b0, uint32_t b1) {
    asm volatile(
        "mma.sync.aligned.m16n8k16.row.col.f32.f16.f16.f32 "
        "{%0,%1,%2,%3},{%4,%5,%6,%7},{%8,%9},{%0,%1,%2,%3};\n"
        : "+f"(c[0]), "+f"(c[1]), "+f"(c[2]), "+f"(c[3])
        : "r"(a[0]), "r"(a[1]), "r"(a[2]), "r"(a[3]), "r"(b0), "r"(b1));
}
// fp16 mma, fp16 accumulate (full-rate probe; used for low-order terms only)
__device__ __forceinline__ void mma16hh(uint32_t* c, const uint32_t* a, uint32_t b0, uint32_t b1) {
    asm volatile(
        "mma.sync.aligned.m16n8k16.row.col.f16.f16.f16.f16 "
        "{%0,%1},{%2,%3,%4,%5},{%6,%7},{%0,%1};\n"
        : "+r"(c[0]), "+r"(c[1])
        : "r"(a[0]), "r"(a[1]), "r"(a[2]), "r"(a[3]), "r"(b0), "r"(b1));
}

// fp16 packing
__device__ __forceinline__ uint32_t packh16(float e, float o) {
    __half2 t = __floats2half2_rn(e, o);
    return *reinterpret_cast<const uint32_t*>(&t);
}
__device__ __forceinline__ uint32_t packl16(float e, float o) {
    float he = __half2float(__float2half_rn(e));
    float ho = __half2float(__float2half_rn(o));
    return packh16(e - he, o - ho);
}
__device__ __forceinline__ void sstore16(f16* oh, f16* ol, int i, float v) {
    f16 h = __float2half_rn(v);
    oh[i] = h;
    ol[i] = __float2half_rn(v - __half2float(h));
}

// ---------------- fused split pass ----------
#define NHS_ (B_ * S_ * HID_)
#define NWQ_ (HID_ * HID_)
#define NWKV_ (2 * NKV_ * HD_ * HID_)

__global__ void split4_kernel(const float* __restrict__ hs, const float* __restrict__ Wq,
                              const float* __restrict__ Wkv, const float* __restrict__ Wd)
{
    int t = blockIdx.x * blockDim.x + threadIdx.x;
    const int q0 = NHS_ / 4, q1 = q0 + NWQ_ / 4, q2 = q1 + NWKV_ / 4;
    if (t < q0) {
        int i = t * 4;
        float4 x = *(const float4*)(hs + i);
        *(uint32_t*)(g_hsh + i)     = packh16(x.x, x.y);
        *(uint32_t*)(g_hsh + i + 2) = packh16(x.z, x.w);
        *(uint32_t*)(g_hsl + i)     = packl16(x.x, x.y);
        *(uint32_t*)(g_hsl + i + 2) = packl16(x.z, x.w);
    } else {
        const float* src;
        f16* dst;
        int i;
        if (t < q1)      { src = Wq;  dst = g_w;         i = (t - q0) * 4; }
        else if (t < q2) { src = Wkv; dst = g_w + NWQ_;  i = (t - q1) * 4; }
        else             { src = Wd;  dst = g_wd;        i = (t - q2) * 4; }
        float4 x = *(const float4*)(src + i);
        *(uint32_t*)(dst + i)     = packh16(x.x, x.y);
        *(uint32_t*)(dst + i + 2) = packh16(x.z, x.w);
    }
}

// ------------- NT GEMM: 512 thr, 128x256x32, fp16 A-split x2, 3-stage --------
#define GBM 128
#define GBN 256
#define GBK 32
#define ARS 40
#define NSTG 3
#define AH_STG (GBM * ARS)
#define STGH ((2 * GBM + GBN) * ARS)
#define GSMEM (NSTG * STGH * 2)

__global__ __launch_bounds__(512, 1) void gemm_f16x2(
    const f16* __restrict__ Ah, const f16* __restrict__ Al,
    const f16* __restrict__ Wh,
    const float* __restrict__ bias, float* __restrict__ C,
    int N, int K, int mode)
{
    extern __shared__ f16 smh[];

    int tid = threadIdx.x, lane = tid & 31, wid = tid >> 5;
    int g = lane >> 2, tg = lane & 3;
    int wm = (wid & 3) << 5;
    int wn = (wid >> 2) << 6;
    int m0 = blockIdx.y * GBM, n0 = blockIdx.x * GBN;
    const f16* Abh = Ah + (size_t)m0 * K;
    const f16* Abl = Al + (size_t)m0 * K;
    const f16* Bbh = Wh + (size_t)n0 * K;

    float acc[2][8][4];
#pragma unroll
    for (int i = 0; i < 2; i++)
#pragma unroll
        for (int j = 0; j < 8; j++)
#pragma unroll
            for (int c = 0; c < 4; c++) acc[i][j][c] = 0.f;

    int nk = K / GBK;

    auto load_tile = [&](int kt, int s) {
        int k0 = kt * GBK;
        f16* ah = smh + s * STGH;
        f16* al = ah + AH_STG;
        f16* bh = al + AH_STG;
        {
            int row = tid >> 2, q = tid & 3;
            size_t go = (size_t)row * K + k0 + q * 8;
            cp16(&ah[row * ARS + q * 8], Abh + go);
            cp16(&al[row * ARS + q * 8], Abl + go);
        }
#pragma unroll
        for (int i = 0; i < 2; i++) {
            int idx = tid + i * 512;
            int row = idx >> 2, q = idx & 3;
            size_t go = (size_t)row * K + k0 + q * 8;
            cp16(&bh[row * ARS + q * 8], Bbh + go);
        }
    };

    load_tile(0, 0); cp_commit();
    load_tile(1, 1); cp_commit();

    for (int kt = 0; kt < nk; kt++) {
        if (kt == nk - 1) cp_wait0(); else cp_wait1();
        __syncthreads();
        if (kt + 2 < nk) { load_tile(kt + 2, (kt + 2) % NSTG); cp_commit(); }

        int s = kt % NSTG;
        const f16* ah = smh + s * STGH;
        const f16* al = ah + AH_STG;
        const f16* bh = al + AH_STG;

#pragma unroll
        for (int k16 = 0; k16 < 2; k16++) {
            int kk = k16 * 16 + (lane >> 4) * 8;
            uint32_t fah[2][4], fal[2][4];
#pragma unroll
            for (int mi = 0; mi < 2; mi++) {
                int aoff = (wm + mi * 16 + (lane & 15)) * ARS + kk;
                ldsm4(fah[mi], ah + aoff);
                ldsm4(fal[mi], al + aoff);
            }
#pragma unroll
            for (int njp = 0; njp < 4; njp++) {
                int boff = (wn + njp * 16 + (lane & 15)) * ARS + kk;
                uint32_t fbh[4];
                ldsm4(fbh, bh + boff);
#pragma unroll
                for (int mi = 0; mi < 2; mi++) {
                    mma16h(acc[mi][2 * njp],     fah[mi], fbh[0], fbh[2]);
                    mma16h(acc[mi][2 * njp + 1], fah[mi], fbh[1], fbh[3]);
                }
#pragma unroll
                for (int mi = 0; mi < 2; mi++) {
                    mma16h(acc[mi][2 * njp],     fal[mi], fbh[0], fbh[2]);
                    mma16h(acc[mi][2 * njp + 1], fal[mi], fbh[1], fbh[3]);
                }
            }
        }
    }

    // epilogue
#pragma unroll
    for (int mi = 0; mi < 2; mi++) {
#pragma unroll
        for (int nj = 0; nj < 8; nj++) {
            int col = n0 + wn + nj * 8 + tg * 2;
#pragma unroll
            for (int half = 0; half < 2; half++) {
                int row = m0 + wm + mi * 16 + g + half * 8;
                float v0 = acc[mi][nj][half * 2], v1 = acc[mi][nj][half * 2 + 1];
                if (mode == 0) {
                    C[(size_t)row * N + col]     = v0 + bias[col];
                    C[(size_t)row * N + col + 1] = v1 + bias[col + 1];
                } else {
                    int bb = row >> 11, s2 = row & (S_ - 1);
                    if (col < HID_) {
                        int hh = col >> 7, d = col & 127;
                        size_t o = (((size_t)bb * NH_ + hh) * S_ + s2) * HD_ + d;
                        g_qf[o] = v0; g_qf[o + 1] = v1;
                    } else {
                        int n2 = col - HID_;
                        int kh = n2 >> 8, cc = n2 & 255;
                        if (cc < 128) {
                            size_t o = (((size_t)bb * NKV_ + kh) * S_ + s2) * HD_ + cc;
                            g_kf[o] = v0; g_kf[o + 1] = v1;
                        } else {
                            int d = cc - 128;
                            size_t o = (((size_t)bb * NKV_ + kh) * S_ + s2) * HD_ + d;
                            *(uint32_t*)(g_vh + o) = packh16(v0, v1);
                        }
                    }
                }
            }
        }
    }
}

// ---------------- RoPE + split (q -> f16 hi/lo, k -> f16) ----------------
__global__ void rope_split(const float* __restrict__ cosT, const float* __restrict__ sinT)
{
    int idx = blockIdx.x * blockDim.x + threadIdx.x;
    int d = idx & 63;
    int r = idx >> 6;
    int s = r & (S_ - 1);
    int hh = r >> 11;
    float c1 = cosT[s * HD_ + d],      s1 = sinT[s * HD_ + d];
    float c2 = cosT[s * HD_ + d + 64], s2 = sinT[s * HD_ + d + 64];
    if (hh < B_ * NH_) {
        const float* p = g_qf + (size_t)r * HD_;
        f16* oh = g_qh + (size_t)r * HD_;
        f16* ol = g_ql + (size_t)r * HD_;
        float x1 = p[d], x2 = p[d + 64];
        sstore16(oh, ol, d,      x1 * c1 - x2 * s1);
        sstore16(oh, ol, d + 64, x2 * c2 + x1 * s2);
    } else {
        size_t rr = (size_t)r - (size_t)B_ * NH_ * S_;
        const float* p = g_kf + rr * HD_;
        f16* ok = g_kh + rr * HD_;
        float x1 = p[d], x2 = p[d + 64];
        ok[d]      = __float2half_rn(x1 * c1 - x2 * s1);
        ok[d + 64] = __float2half_rn(x2 * c2 + x1 * s2);
    }
}

// ---------------- Flash attention, fp16 2-term, f16-acc lo probe -------------
#define AQ 128
#define AK 64
#define RS_ 136
#define KVT (AK * RS_)          // one tile (K or V): 8704 halves
#define KVSTG (2 * KVT)         // K + V per stage
#define SBOFF (2 * AQ * RS_)    // Q hi + lo: 34816 halves
#define ASMEM ((SBOFF + 2 * KVSTG) * 2)   // 139264 bytes

__global__ __launch_bounds__(256, 1) void attn_f16()
{
    extern __shared__ f16 smf[];
    f16* Qh = smf;
    f16* Ql = Qh + AQ * RS_;

    int qt = gridDim.x - 1 - blockIdx.x;
    int h = blockIdx.y, b = blockIdx.z;
    int tid = threadIdx.x, lane = tid & 31, wid = tid >> 5;
    int g = lane >> 2, tg = lane & 3;

    const f16* Qbh = g_qh + (((size_t)b * NH_ + h) * S_ + (size_t)qt * AQ) * HD_;
    const f16* Qbl = g_ql + (((size_t)b * NH_ + h) * S_ + (size_t)qt * AQ) * HD_;
    const f16* Kb  = g_kh + ((size_t)b * NKV_ + (h >> 2)) * S_ * HD_;
    const f16* Vb  = g_vh + ((size_t)b * NKV_ + (h >> 2)) * S_ * HD_;

#pragma unroll
    for (int i = 0; i < 8; i++) {
        int idx = tid + i * 256;
        int row = idx >> 4, q = idx & 15;
        size_t go = (size_t)row * HD_ + q * 8;
        cp16(&Qh[row * RS_ + q * 8], Qbh + go);
        cp16(&Ql[row * RS_ + q * 8], Qbl + go);
    }
    cp_commit();

    auto load_kv = [&](int kt, int s) {
        f16* base = smf + SBOFF + s * KVSTG;
#pragma unroll
        for (int i = 0; i < 4; i++) {
            int idx = tid + i * 256;
            int row = idx >> 4, q = idx & 15;
            size_t go = (size_t)(kt * AK + row) * HD_ + q * 8;
            int so = row * RS_ + q * 8;
            cp16(&base[so],       Kb + go);
            cp16(&base[KVT + so], Vb + go);
        }
    };

    float o[16][4];
#pragma unroll
    for (int j = 0; j < 16; j++)
#pragma unroll
        for (int c = 0; c < 4; c++) o[j][c] = 0.f;
    float m0 = -1e30f, m1 = -1e30f, l0 = 0.f, l1 = 0.f;
    const float scale = 0.08838834764831845f;
    int pr = wid * 16;

    int nkt = (qt + 1) * 2;
    load_kv(0, 0); cp_commit();

    for (int kt = 0; kt < nkt; kt++) {
        cp_wait0();
        __syncthreads();
        if (kt + 1 < nkt) { load_kv(kt + 1, (kt + 1) & 1); cp_commit(); }

        f16* Kh = smf + SBOFF + (kt & 1) * KVSTG;
        f16* Vh = Kh + KVT;

        // S = Q K^T: hi-term f32-acc, lo-term f16-acc (folded after the loop)
        float sf[8][4];
        uint32_t slo[8][2];
#pragma unroll
        for (int j = 0; j < 8; j++) {
            sf[j][0] = sf[j][1] = sf[j][2] = sf[j][3] = 0.f;
            slo[j][0] = slo[j][1] = 0u;
        }

#pragma unroll
        for (int k16 = 0; k16 < 8; k16++) {
            int kk = k16 * 16 + (lane >> 4) * 8;
            int aoff = (pr + (lane & 15)) * RS_ + kk;
            uint32_t fah[4], fal[4];
            ldsm4(fah, Qh + aoff);
            ldsm4(fal, Ql + aoff);
#pragma unroll
            for (int np2 = 0; np2 < 2; np2++) {
                uint32_t fb[2][4];
#pragma unroll
                for (int u = 0; u < 2; u++) {
                    int boff = ((np2 * 2 + u) * 16 + (lane & 15)) * RS_ + kk;
                    ldsm4(fb[u], Kh + boff);
                }
                // hi pass: q_hi * k, f32 acc (4 independent accs)
#pragma unroll
                for (int u = 0; u < 2; u++) {
                    int j = (np2 * 2 + u) * 2;
                    mma16h(sf[j],     fah, fb[u][0], fb[u][2]);
                    mma16h(sf[j + 1], fah, fb[u][1], fb[u][3]);
                }
                // lo pass: q_lo * k, f16 acc
#pragma unroll
                for (int u = 0; u < 2; u++) {
                    int j = (np2 * 2 + u) * 2;
                    mma16hh(slo[j],     fal, fb[u][0], fb[u][2]);
                    mma16hh(slo[j + 1], fal, fb[u][1], fb[u][3]);
                }
            }
        }
        // fold f16-acc lo scores into f32 scores
#pragma unroll
        for (int j = 0; j < 8; j++) {
            __half2 u0 = *reinterpret_cast<__half2*>(&slo[j][0]);
            __half2 u1 = *reinterpret_cast<__half2*>(&slo[j][1]);
            sf[j][0] += __low2float(u0);  sf[j][1] += __high2float(u0);
            sf[j][2] += __low2float(u1);  sf[j][3] += __high2float(u1);
        }

        int row0 = qt * AQ + wid * 16 + g;
        int colb = kt * AK + tg * 2;
        float mx0 = -1e30f, mx1 = -1e30f;
#pragma unroll
        for (int nj = 0; nj < 8; nj++) {
#pragma unroll
            for (int c = 0; c < 4; c++) {
                int col = colb + nj * 8 + (c & 1);
                int row = row0 + ((c & 2) ? 8 : 0);
                float v = sf[nj][c] * scale;
                if (col > row) v = -1e30f;
                sf[nj][c] = v;
                if (c < 2) mx0 = fmaxf(mx0, v); else mx1 = fmaxf(mx1, v);
            }
        }
        mx0 = fmaxf(mx0, __shfl_xor_sync(0xffffffffu, mx0, 1));
        mx0 = fmaxf(mx0, __shfl_xor_sync(0xffffffffu, mx0, 2));
        mx1 = fmaxf(mx1, __shfl_xor_sync(0xffffffffu, mx1, 1));
        mx1 = fmaxf(mx1, __shfl_xor_sync(0xffffffffu, mx1, 2));

        float mn0 = fmaxf(m0, mx0), mn1 = fmaxf(m1, mx1);
        float al0 = __expf(m0 - mn0), al1 = __expf(m1 - mn1);
        m0 = mn0; m1 = mn1;

        float rs0 = 0.f, rs1 = 0.f;
#pragma unroll
        for (int nj = 0; nj < 8; nj++) {
            float p0 = __expf(sf[nj][0] - mn0), p1 = __expf(sf[nj][1] - mn0);
            float p2 = __expf(sf[nj][2] - mn1), p3 = __expf(sf[nj][3] - mn1);
            sf[nj][0] = p0; sf[nj][1] = p1; sf[nj][2] = p2; sf[nj][3] = p3;
            rs0 += p0 + p1; rs1 += p2 + p3;
        }
        rs0 += __shfl_xor_sync(0xffffffffu, rs0, 1);
        rs0 += __shfl_xor_sync(0xffffffffu, rs0, 2);
        rs1 += __shfl_xor_sync(0xffffffffu, rs1, 1);
        rs1 += __shfl_xor_sync(0xffffffffu, rs1, 2);
        l0 = l0 * al0 + rs0;
        l1 = l1 * al1 + rs1;
#pragma unroll
        for (int j = 0; j < 16; j++) {
            o[j][0] *= al0; o[j][1] *= al0; o[j][2] *= al1; o[j][3] *= al1;
        }

        // O += P @ V: P fp16 hi/lo (2 passes, f32 acc), V single fp16
#pragma unroll
        for (int t = 0; t < 4; t++) {
            uint32_t pah[4], pal[4];
            pah[0] = packh16(sf[2 * t][0], sf[2 * t][1]);
            pal[0] = packl16(sf[2 * t][0], sf[2 * t][1]);
            pah[1] = packh16(sf[2 * t][2], sf[2 * t][3]);
            pal[1] = packl16(sf[2 * t][2], sf[2 * t][3]);
            pah[2] = packh16(sf[2 * t + 1][0], sf[2 * t + 1][1]);
            pal[2] = packl16(sf[2 * t + 1][0], sf[2 * t + 1][1]);
            pah[3] = packh16(sf[2 * t + 1][2], sf[2 * t + 1][3]);
            pal[3] = packl16(sf[2 * t + 1][2], sf[2 * t + 1][3]);
#pragma unroll
            for (int dp = 0; dp < 4; dp++) {
                uint32_t fv[2][4];
#pragma unroll
                for (int u = 0; u < 2; u++) {
                    int dj = dp * 2 + u;
                    int voff = (t * 16 + (lane & 15)) * RS_ + dj * 16 + (lane >> 4) * 8;
                    ldsm4t(fv[u], Vh + voff);
                }
#pragma unroll
                for (int u = 0; u < 2; u++) {
                    int dj = dp * 2 + u;
                    mma16h(o[2 * dj],     pah, fv[u][0], fv[u][1]);
                    mma16h(o[2 * dj + 1], pah, fv[u][2], fv[u][3]);
                }
#pragma unroll
                for (int u = 0; u < 2; u++) {
                    int dj = dp * 2 + u;
                    mma16h(o[2 * dj],     pal, fv[u][0], fv[u][1]);
                    mma16h(o[2 * dj + 1], pal, fv[u][2], fv[u][3]);
                }
            }
        }
    }

    // epilogue: O/l -> ctx split to fp16 hi/lo
    float il0 = 1.f / l0, il1 = 1.f / l1;
    int row0 = qt * AQ + wid * 16 + g;
    size_t b0 = ((size_t)b * S_ + row0) * HID_ + (size_t)h * HD_;
    size_t b1 = b0 + (size_t)8 * HID_;
#pragma unroll
    for (int nj = 0; nj < 16; nj++) {
        int d = nj * 8 + tg * 2;
        float v0 = o[nj][0] * il0, v1 = o[nj][1] * il0;
        *(uint32_t*)(g_ch + b0 + d) = packh16(v0, v1);
        *(uint32_t*)(g_cl + b0 + d) = packl16(v0, v1);
        float w0 = o[nj][2] * il1, w1 = o[nj][3] * il1;
        *(uint32_t*)(g_ch + b1 + d) = packh16(w0, w1);
        *(uint32_t*)(g_cl + b1 + d) = packl16(w0, w1);
    }
}

// ---------------- launch ----------------
extern "C" void kernel_launch(void* const* d_in, const int* in_sizes, int n_in,
                              void* d_out, int out_size)
{
    const float* hs   = (const float*)d_in[0];
    const float* cosT = (const float*)d_in[2];
    const float* sinT = (const float*)d_in[3];
    const float* Wq   = (const float*)d_in[4];
    const float* Wkv  = (const float*)d_in[5];
    const float* Wd   = (const float*)d_in[6];
    const float* bd   = (const float*)d_in[7];
    float* out = (float*)d_out;

    cudaFuncSetAttribute(gemm_f16x2, cudaFuncAttributeMaxDynamicSharedMemorySize, GSMEM);
    cudaFuncSetAttribute(attn_f16, cudaFuncAttributeMaxDynamicSharedMemorySize, ASMEM);

    void *hsh, *hsl, *w, *wd, *ch, *cl;
    cudaGetSymbolAddress(&hsh, g_hsh);  cudaGetSymbolAddress(&hsl, g_hsl);
    cudaGetSymbolAddress(&w,   g_w);    cudaGetSymbolAddress(&wd,  g_wd);
    cudaGetSymbolAddress(&ch,  g_ch);   cudaGetSymbolAddress(&cl,  g_cl);

    const int total4 = (NHS_ + NWQ_ + NWKV_ + NWQ_) / 4;
    split4_kernel<<<total4 / 256, 256>>>(hs, Wq, Wkv, Wd);

    gemm_f16x2<<<dim3((HID_ + 2 * NKV_ * HD_) / GBN, (B_ * S_) / GBM), 512, GSMEM>>>(
        (const f16*)hsh, (const f16*)hsl, (const f16*)w,
        bd, out, HID_ + 2 * NKV_ * HD_, HID_, 1);

    rope_split<<<(B_ * (NH_ + NKV_) * S_ * 64) / 256, 256>>>(cosT, sinT);

    attn_f16<<<dim3(S_ / AQ, NH_, B_), 256, ASMEM>>>();

    gemm_f16x2<<<dim3(HID_ / GBN, (B_ * S_) / GBM), 512, GSMEM>>>(
        (const f16*)ch, (const f16*)cl, (const f16*)wd,
        bd, out, HID_, HID_, 0);
}